// round 1
// baseline (speedup 1.0000x reference)
#include <cuda_runtime.h>
#include <math.h>
#include <stdint.h>

// Problem constants (fixed by the dataset)
#define MAXN 100000
#define MAXE 1600000
#define MAXT (MAXN + MAXE)
#define BSZ  1024
#define HC   128   // H*C
#define NH   4
#define CH   30
#define SEQL 20

// ---------------- scratch (static device globals; no allocation) -------------
__device__ float d_h[(size_t)MAXN * 128];   // GAT h; later reused as h3
__device__ float d_g1[(size_t)MAXN * 128];  // GAT out g1; later reused as g3
__device__ float d_h2[(size_t)MAXN * 64];
__device__ float d_g2[(size_t)MAXN * 64];
__device__ float d_as[MAXN * 4];
__device__ float d_ad[MAXN * 4];
__device__ int   d_deg[MAXN];
__device__ int   d_rowptr[MAXN + 1];
__device__ int   d_cursor[MAXN];
__device__ int   d_col[MAXT];
__device__ int   d_bsums[1024];
__device__ float d_dinv[MAXN];
__device__ float d_pool[BSZ * 128];
__device__ float d_cntb[BSZ];
__device__ float d_s1[BSZ * 64 * 18];
__device__ float d_s2[BSZ * 64 * 16];
__device__ float d_sfc[BSZ * 64];

__device__ __forceinline__ float lrelu(float x, float s) { return x >= 0.f ? x : s * x; }
__device__ __forceinline__ float warpMax(float v) {
#pragma unroll
    for (int o = 16; o > 0; o >>= 1) v = fmaxf(v, __shfl_xor_sync(0xffffffffu, v, o));
    return v;
}
__device__ __forceinline__ float warpSum(float v) {
#pragma unroll
    for (int o = 16; o > 0; o >>= 1) v += __shfl_xor_sync(0xffffffffu, v, o);
    return v;
}

// ---------------- K1: h = x @ W_gat ; a_s, a_d ------------------------------
// block = 128 threads (1 thread per channel), 16 nodes per block
__global__ void k_gat_node(const float* __restrict__ x, const float* __restrict__ Wg,
                           const float* __restrict__ asrc, const float* __restrict__ adst, int n) {
    int c = threadIdx.x;
    float w[9];
#pragma unroll
    for (int f = 0; f < 9; f++) w[f] = Wg[f * 128 + c];
    float atts = asrc[c], attd = adst[c];
    __shared__ float sx[16 * 9];
    int base = blockIdx.x * 16;
    int cnt = min(16, n - base);
    if (cnt <= 0) return;
    for (int i = threadIdx.x; i < cnt * 9; i += 128) sx[i] = x[base * 9 + i];
    __syncthreads();
    int wid = c >> 5;
    for (int t = 0; t < cnt; t++) {
        float h = 0.f;
#pragma unroll
        for (int f = 0; f < 9; f++) h += sx[t * 9 + f] * w[f];
        d_h[(size_t)(base + t) * 128 + c] = h;
        float vs = warpSum(h * atts);
        float vd = warpSum(h * attd);
        if ((c & 31) == 0) {
            d_as[(base + t) * 4 + wid] = vs;
            d_ad[(base + t) * 4 + wid] = vd;
        }
    }
}

// ---------------- CSR build --------------------------------------------------
__global__ void k_deg_init(int n) {
    int i = blockIdx.x * blockDim.x + threadIdx.x;
    if (i < n) d_deg[i] = 1;  // self loop
}
__global__ void k_count(const int* __restrict__ ei, int E) {
    for (int e = blockIdx.x * blockDim.x + threadIdx.x; e < E; e += gridDim.x * blockDim.x)
        atomicAdd(&d_deg[ei[E + e]], 1);
}
__global__ void k_scan1(int n) {
    __shared__ int ss[512];
    int idx = blockIdx.x * 512 + threadIdx.x;
    int val = (idx < n) ? d_deg[idx] : 0;
    ss[threadIdx.x] = val;
    __syncthreads();
#pragma unroll
    for (int off = 1; off < 512; off <<= 1) {
        int t = (threadIdx.x >= off) ? ss[threadIdx.x - off] : 0;
        __syncthreads();
        ss[threadIdx.x] += t;
        __syncthreads();
    }
    if (idx < n) d_rowptr[idx] = ss[threadIdx.x] - val;  // exclusive
    if (threadIdx.x == 511) d_bsums[blockIdx.x] = ss[511];
}
__global__ void k_scan2(int nb) {
    __shared__ int ss[512];
    int v = (threadIdx.x < nb) ? d_bsums[threadIdx.x] : 0;
    ss[threadIdx.x] = v;
    __syncthreads();
#pragma unroll
    for (int off = 1; off < 512; off <<= 1) {
        int t = (threadIdx.x >= off) ? ss[threadIdx.x - off] : 0;
        __syncthreads();
        ss[threadIdx.x] += t;
        __syncthreads();
    }
    if (threadIdx.x < nb) d_bsums[threadIdx.x] = ss[threadIdx.x] - v;  // exclusive
}
__global__ void k_scan3(int n, int tot) {
    int idx = blockIdx.x * 512 + threadIdx.x;
    if (idx < n) d_rowptr[idx] += d_bsums[blockIdx.x];
    if (idx == 0) d_rowptr[n] = tot;
}
__global__ void k_selfloop(int n) {
    int i = blockIdx.x * blockDim.x + threadIdx.x;
    if (i < n) {
        int p = d_rowptr[i];
        d_col[p] = i;
        d_cursor[i] = p + 1;
        d_dinv[i] = rsqrtf((float)d_deg[i]);
    }
}
__global__ void k_scatter(const int* __restrict__ ei, int E) {
    for (int e = blockIdx.x * blockDim.x + threadIdx.x; e < E; e += gridDim.x * blockDim.x) {
        int s = ei[e], d = ei[E + e];
        int pos = atomicAdd(&d_cursor[d], 1);
        d_col[pos] = s;
    }
}

// ---------------- K3: GAT aggregate (one warp per dst node) ------------------
__global__ void k_gat_agg(const float* __restrict__ bias, int n) {
    int warp = (blockIdx.x * blockDim.x + threadIdx.x) >> 5;
    int lane = threadIdx.x & 31;
    if (warp >= n) return;
    int i = warp;
    int start = d_rowptr[i], end = d_rowptr[i + 1];
    float4 ad4 = *(const float4*)(d_ad + 4 * i);
    float m0 = -1e30f, m1 = -1e30f, m2 = -1e30f, m3 = -1e30f;
    for (int j = start + lane; j < end; j += 32) {
        int s = d_col[j];
        float4 a = *(const float4*)(d_as + 4 * s);
        m0 = fmaxf(m0, lrelu(a.x + ad4.x, 0.2f));
        m1 = fmaxf(m1, lrelu(a.y + ad4.y, 0.2f));
        m2 = fmaxf(m2, lrelu(a.z + ad4.z, 0.2f));
        m3 = fmaxf(m3, lrelu(a.w + ad4.w, 0.2f));
    }
    m0 = warpMax(m0); m1 = warpMax(m1); m2 = warpMax(m2); m3 = warpMax(m3);
    float s0 = 0.f, s1 = 0.f, s2 = 0.f, s3 = 0.f;
    for (int j = start + lane; j < end; j += 32) {
        int s = d_col[j];
        float4 a = *(const float4*)(d_as + 4 * s);
        s0 += expf(lrelu(a.x + ad4.x, 0.2f) - m0);
        s1 += expf(lrelu(a.y + ad4.y, 0.2f) - m1);
        s2 += expf(lrelu(a.z + ad4.z, 0.2f) - m2);
        s3 += expf(lrelu(a.w + ad4.w, 0.2f) - m3);
    }
    s0 = warpSum(s0); s1 = warpSum(s1); s2 = warpSum(s2); s3 = warpSum(s3);
    float i0 = 1.f / (s0 + 1e-16f), i1 = 1.f / (s1 + 1e-16f);
    float i2 = 1.f / (s2 + 1e-16f), i3 = 1.f / (s3 + 1e-16f);
    int hh = lane >> 3;  // head of this lane's 4 channels
    float mm = hh < 2 ? (hh == 0 ? m0 : m1) : (hh == 2 ? m2 : m3);
    float ii = hh < 2 ? (hh == 0 ? i0 : i1) : (hh == 2 ? i2 : i3);
    float aad = hh < 2 ? (hh == 0 ? ad4.x : ad4.y) : (hh == 2 ? ad4.z : ad4.w);
    float4 acc = make_float4(0.f, 0.f, 0.f, 0.f);
    for (int j = start; j < end; j++) {
        int s = d_col[j];
        float4 a = *(const float4*)(d_as + 4 * s);
        float av = hh < 2 ? (hh == 0 ? a.x : a.y) : (hh == 2 ? a.z : a.w);
        float alpha = expf(lrelu(av + aad, 0.2f) - mm) * ii;
        const float4 hv = *(const float4*)(d_h + (size_t)s * 128 + 4 * lane);
        acc.x += alpha * hv.x; acc.y += alpha * hv.y;
        acc.z += alpha * hv.z; acc.w += alpha * hv.w;
    }
    float4 b4 = *(const float4*)(bias + 4 * lane);
    float4 o;
    o.x = lrelu(acc.x + b4.x, 0.01f);
    o.y = lrelu(acc.y + b4.y, 0.01f);
    o.z = lrelu(acc.z + b4.z, 0.01f);
    o.w = lrelu(acc.w + b4.w, 0.01f);
    *(float4*)(d_g1 + (size_t)i * 128 + 4 * lane) = o;
}

// ---------------- dense per-node matmuls ------------------------------------
// h2 = g1[N,128] @ W2[128,64]
__global__ void k_mm1(const float* __restrict__ W, int n) {
    __shared__ float sW[128 * 64];
    __shared__ float sX[4 * 128];
    for (int i = threadIdx.x; i < 128 * 64; i += 256) sW[i] = W[i];
    for (int base = blockIdx.x * 4; base < n; base += gridDim.x * 4) {
        __syncthreads();
        int cnt = min(4, n - base);
        for (int i = threadIdx.x; i < cnt * 128; i += 256) sX[i] = d_g1[(size_t)base * 128 + i];
        __syncthreads();
        int ln = threadIdx.x >> 6, c = threadIdx.x & 63;
        if (ln < cnt) {
            float acc = 0.f;
#pragma unroll 16
            for (int k = 0; k < 128; k++) acc += sX[ln * 128 + k] * sW[k * 64 + c];
            d_h2[(size_t)(base + ln) * 64 + c] = acc;
        }
    }
}
// h3 = g2[N,64] @ W3[64,128]  (writes into d_h)
__global__ void k_mm2(const float* __restrict__ W, int n) {
    __shared__ float sW[64 * 128];
    __shared__ float sX[2 * 64];
    for (int i = threadIdx.x; i < 64 * 128; i += 256) sW[i] = W[i];
    for (int base = blockIdx.x * 2; base < n; base += gridDim.x * 2) {
        __syncthreads();
        int cnt = min(2, n - base);
        for (int i = threadIdx.x; i < cnt * 64; i += 256) sX[i] = d_g2[(size_t)base * 64 + i];
        __syncthreads();
        int ln = threadIdx.x >> 7, c = threadIdx.x & 127;
        if (ln < cnt) {
            float acc = 0.f;
#pragma unroll 16
            for (int k = 0; k < 64; k++) acc += sX[ln * 64 + k] * sW[k * 128 + c];
            d_h[(size_t)(base + ln) * 128 + c] = acc;
        }
    }
}

// ---------------- GCN aggregates (warp per dst node) -------------------------
__global__ void k_gcn64(const float* __restrict__ bias, int n) {
    int warp = (blockIdx.x * blockDim.x + threadIdx.x) >> 5;
    int lane = threadIdx.x & 31;
    if (warp >= n) return;
    int i = warp;
    int start = d_rowptr[i], end = d_rowptr[i + 1];
    float dvi = d_dinv[i];
    float ax = 0.f, ay = 0.f;
    for (int j = start; j < end; j++) {
        int s = d_col[j];
        float w = d_dinv[s] * dvi;
        float2 v = *(const float2*)(d_h2 + (size_t)s * 64 + 2 * lane);
        ax += w * v.x; ay += w * v.y;
    }
    float2 b2 = *(const float2*)(bias + 2 * lane);
    float2 o;
    o.x = lrelu(ax + b2.x, 0.01f);
    o.y = lrelu(ay + b2.y, 0.01f);
    *(float2*)(d_g2 + (size_t)i * 64 + 2 * lane) = o;
}
__global__ void k_gcn128(const float* __restrict__ bias, int n) {
    int warp = (blockIdx.x * blockDim.x + threadIdx.x) >> 5;
    int lane = threadIdx.x & 31;
    if (warp >= n) return;
    int i = warp;
    int start = d_rowptr[i], end = d_rowptr[i + 1];
    float dvi = d_dinv[i];
    float4 acc = make_float4(0.f, 0.f, 0.f, 0.f);
    for (int j = start; j < end; j++) {
        int s = d_col[j];
        float w = d_dinv[s] * dvi;
        float4 v = *(const float4*)(d_h + (size_t)s * 128 + 4 * lane);
        acc.x += w * v.x; acc.y += w * v.y; acc.z += w * v.z; acc.w += w * v.w;
    }
    float4 b4 = *(const float4*)(bias + 4 * lane);
    float4 o;
    o.x = lrelu(acc.x + b4.x, 0.01f);
    o.y = lrelu(acc.y + b4.y, 0.01f);
    o.z = lrelu(acc.z + b4.z, 0.01f);
    o.w = lrelu(acc.w + b4.w, 0.01f);
    *(float4*)(d_g1 + (size_t)i * 128 + 4 * lane) = o;
}

// ---------------- global mean pool -------------------------------------------
__global__ void k_zero_pool(int b) {
    int i = blockIdx.x * blockDim.x + threadIdx.x;
    if (i < b * 128) d_pool[i] = 0.f;
    if (i < b) d_cntb[i] = 0.f;
}
__global__ void k_cntb(const int* __restrict__ batch, int n) {
    int i = blockIdx.x * blockDim.x + threadIdx.x;
    if (i < n) atomicAdd(&d_cntb[batch[i]], 1.f);
}
__global__ void k_pool_acc(const int* __restrict__ batch, int n) {
    int total = n * 128;
    for (int idx = blockIdx.x * blockDim.x + threadIdx.x; idx < total; idx += gridDim.x * blockDim.x) {
        int node = idx >> 7, c = idx & 127;
        atomicAdd(&d_pool[batch[node] * 128 + c], d_g1[idx]);
    }
}
__global__ void k_pool_div(int b) {
    int i = blockIdx.x * blockDim.x + threadIdx.x;
    if (i < b * 128) d_pool[i] /= fmaxf(d_cntb[i >> 7], 1.f);
}

// ---------------- sequence branch -------------------------------------------
__global__ void k_conv1(const float* __restrict__ seq, const float* __restrict__ w,
                        const float* __restrict__ bconv,
                        const float* __restrict__ g, const float* __restrict__ be,
                        const float* __restrict__ m, const float* __restrict__ v, int b) {
    __shared__ float sw[64 * 30 * 3];
    for (int i = threadIdx.x; i < 64 * 30 * 3; i += 256) sw[i] = w[i];
    __syncthreads();
    int total = b * 64 * 18;
    for (int idx = blockIdx.x * blockDim.x + threadIdx.x; idx < total; idx += gridDim.x * blockDim.x) {
        int pos = idx % 18, co = (idx / 18) % 64, bb = idx / (18 * 64);
        float acc = bconv[co];
        const float* xb = seq + bb * (CH * SEQL);
        const float* wp = sw + co * 90;
#pragma unroll
        for (int cin = 0; cin < 30; cin++) {
            const float* xp = xb + cin * 20 + pos;
            acc += xp[0] * wp[cin * 3 + 0] + xp[1] * wp[cin * 3 + 1] + xp[2] * wp[cin * 3 + 2];
        }
        float sc = g[co] * rsqrtf(v[co] + 1e-5f);
        float sh = be[co] - m[co] * sc;
        d_s1[idx] = lrelu(acc * sc + sh, 0.01f);
    }
}
__global__ void k_conv2(const float* __restrict__ w, const float* __restrict__ bconv,
                        const float* __restrict__ g, const float* __restrict__ be,
                        const float* __restrict__ m, const float* __restrict__ v, int b) {
    __shared__ float sw[64 * 64 * 3];  // 48KB
    for (int i = threadIdx.x; i < 64 * 64 * 3; i += 256) sw[i] = w[i];
    __syncthreads();
    int total = b * 64 * 16;
    for (int idx = blockIdx.x * blockDim.x + threadIdx.x; idx < total; idx += gridDim.x * blockDim.x) {
        int pos = idx % 16, co = (idx / 16) % 64, bb = idx / (16 * 64);
        float acc = bconv[co];
        const float* xb = d_s1 + bb * (64 * 18);
        const float* wp = sw + co * 192;
#pragma unroll 8
        for (int cin = 0; cin < 64; cin++) {
            const float* xp = xb + cin * 18 + pos;
            acc += xp[0] * wp[cin * 3 + 0] + xp[1] * wp[cin * 3 + 1] + xp[2] * wp[cin * 3 + 2];
        }
        float sc = g[co] * rsqrtf(v[co] + 1e-5f);
        float sh = be[co] - m[co] * sc;
        d_s2[idx] = lrelu(acc * sc + sh, 0.01f);
    }
}
__global__ void k_fc1(const float* __restrict__ W, const float* __restrict__ bias) {
    __shared__ float sm[1024];
    int b = blockIdx.x;
    for (int k = threadIdx.x; k < 1024; k += 64) sm[k] = d_s2[b * 1024 + k];
    __syncthreads();
    float acc = bias[threadIdx.x];
    for (int k = 0; k < 1024; k++) acc += sm[k] * W[k * 64 + threadIdx.x];
    d_sfc[b * 64 + threadIdx.x] = acc;  // no activation on fc1 output
}

// ---------------- fusion + classifier ----------------------------------------
__global__ void k_head(const float* __restrict__ fusW, const float* __restrict__ fusb,
                       const float* __restrict__ c1W, const float* __restrict__ c1b,
                       const float* __restrict__ c3W, const float* __restrict__ c3b,
                       float* __restrict__ out) {
    __shared__ float comb[192];
    __shared__ float t1[128];
    __shared__ float red[2];
    int b = blockIdx.x, tid = threadIdx.x;
    comb[tid] = d_pool[b * 128 + tid];
    if (tid < 64) comb[128 + tid] = d_sfc[b * 64 + tid];
    __syncthreads();
    float a = fusb[tid];
    for (int k = 0; k < 192; k++) a += comb[k] * fusW[k * 128 + tid];
    t1[tid] = lrelu(a, 0.01f);
    __syncthreads();
    float vred = 0.f;
    if (tid < 64) {
        float acc = c1b[tid];
        for (int k = 0; k < 128; k++) acc += t1[k] * c1W[k * 64 + tid];
        vred = lrelu(acc, 0.01f) * c3W[tid];
    }
    vred = warpSum(vred);
    if ((tid & 31) == 0 && tid < 64) red[tid >> 5] = vred;
    __syncthreads();
    if (tid == 0) out[b] = red[0] + red[1] + c3b[0];
}

// ---------------- launch ------------------------------------------------------
extern "C" void kernel_launch(void* const* d_in, const int* in_sizes, int n_in,
                              void* d_out, int out_size) {
    const float* x      = (const float*)d_in[0];
    const int*   ei     = (const int*)d_in[1];
    const int*   batch  = (const int*)d_in[2];
    const float* seq    = (const float*)d_in[3];
    const float* W_gat  = (const float*)d_in[4];
    const float* att_s  = (const float*)d_in[5];
    const float* att_d  = (const float*)d_in[6];
    const float* b_gat  = (const float*)d_in[7];
    const float* W2     = (const float*)d_in[8];
    const float* b2     = (const float*)d_in[9];
    const float* W3     = (const float*)d_in[10];
    const float* b3     = (const float*)d_in[11];
    const float* c1w    = (const float*)d_in[12];
    const float* c1b    = (const float*)d_in[13];
    const float* c2w    = (const float*)d_in[14];
    const float* c2b    = (const float*)d_in[15];
    const float* bn1g   = (const float*)d_in[16];
    const float* bn1b   = (const float*)d_in[17];
    const float* bn1m   = (const float*)d_in[18];
    const float* bn1v   = (const float*)d_in[19];
    const float* bn2g   = (const float*)d_in[20];
    const float* bn2b   = (const float*)d_in[21];
    const float* bn2m   = (const float*)d_in[22];
    const float* bn2v   = (const float*)d_in[23];
    const float* fc1W   = (const float*)d_in[24];
    const float* fc1b   = (const float*)d_in[25];
    const float* fusW   = (const float*)d_in[26];
    const float* fusb   = (const float*)d_in[27];
    const float* cl1W   = (const float*)d_in[28];
    const float* cl1b   = (const float*)d_in[29];
    const float* cl3W   = (const float*)d_in[30];
    const float* cl3b   = (const float*)d_in[31];
    float* out = (float*)d_out;

    int n = in_sizes[0] / 9;
    int E = in_sizes[1] / 2;
    int b = in_sizes[3] / (CH * SEQL);
    if (n > MAXN || E > MAXE || b > BSZ) return;

    // 1) node transform + attention coefficients
    k_gat_node<<<(n + 15) / 16, 128>>>(x, W_gat, att_s, att_d, n);

    // 2) CSR build (reused by all three convs; also yields degrees for GCN norm)
    k_deg_init<<<(n + 255) / 256, 256>>>(n);
    k_count<<<2048, 256>>>(ei, E);
    int NB = (n + 511) / 512;
    k_scan1<<<NB, 512>>>(n);
    k_scan2<<<1, 512>>>(NB);
    k_scan3<<<NB, 512>>>(n, E + n);
    k_selfloop<<<(n + 255) / 256, 256>>>(n);
    k_scatter<<<2048, 256>>>(ei, E);

    // 3) GAT aggregate -> g1
    k_gat_agg<<<(n + 7) / 8, 256>>>(b_gat, n);

    // 4) GCN conv 2: matmul + aggregate -> g2
    k_mm1<<<2048, 256>>>(W2, n);
    k_gcn64<<<(n + 7) / 8, 256>>>(b2, n);

    // 5) GCN conv 3: matmul + aggregate -> g3 (in d_g1)
    k_mm2<<<2048, 256>>>(W3, n);
    k_gcn128<<<(n + 7) / 8, 256>>>(b3, n);

    // 6) global mean pool
    k_zero_pool<<<(b * 128 + 255) / 256, 256>>>(b);
    k_cntb<<<(n + 255) / 256, 256>>>(batch, n);
    k_pool_acc<<<4096, 256>>>(batch, n);
    k_pool_div<<<(b * 128 + 255) / 256, 256>>>(b);

    // 7) sequence branch
    k_conv1<<<1024, 256>>>(seq, c1w, c1b, bn1g, bn1b, bn1m, bn1v, b);
    k_conv2<<<1024, 256>>>(c2w, c2b, bn2g, bn2b, bn2m, bn2v, b);
    k_fc1<<<b, 64>>>(fc1W, fc1b);

    // 8) fusion + classifier
    k_head<<<b, 128>>>(fusW, fusb, cl1W, cl1b, cl3W, cl3b, out);
}